// round 2
// baseline (speedup 1.0000x reference)
#include <cuda_runtime.h>
#include <math.h>

#define NDEPTH 12
#define DIMN   768
#define NHEAD  12
#define HDIM   64
#define NTOK   577
#define NCLS   1000
#define HIDN   3072
#define BATCH  8
#define ROWS   (BATCH * NTOK)   // 4616
#define PROWS  (BATCH * 576)    // 4608
#define SPAD   640              // padded attention row stride (16B aligned, covers float4 tails)

// ---------------- scratch (static device memory; no allocations) ----------------
__device__ float g_patch[PROWS * DIMN];          // im2col patches
__device__ float g_h[ROWS * DIMN];               // residual stream
__device__ float g_y[ROWS * DIMN];               // LN output / patch-gemm scratch
__device__ float g_qkv[ROWS * 3 * DIMN];         // qkv projections
__device__ float g_att[(size_t)BATCH * NHEAD * NTOK * SPAD];   // attention scores (padded rows)
__device__ float g_o[ROWS * DIMN];               // attention output (B,N,H*HD)
__device__ float g_mid[ROWS * HIDN];             // MLP hidden
__device__ float g_wpt[DIMN * DIMN];             // transposed patch weight
__device__ float g_cls[BATCH * DIMN];            // final-LN cls rows

// ---------------- generic fused SGEMM: C = A[MxK] @ B[KxN] + bias (+epi) ----------
// EPI: 0 = bias, 1 = bias + residual, 2 = bias + exact GELU
// Double-buffered smem pipeline, 128x128 tile, 8x8 per thread, K-step 16.
template <int EPI>
__global__ __launch_bounds__(256) void sgemm_k(
    const float* __restrict__ A, const float* __restrict__ B,
    const float* __restrict__ bias, const float* __restrict__ res,
    float* __restrict__ C, int M, int N, int K)
{
    __shared__ float As[2][16][128];   // transposed: As[buf][k][m]
    __shared__ float Bs[2][16][128];

    int tid = threadIdx.x;
    int m0 = blockIdx.y * 128;
    int n0 = blockIdx.x * 128;
    int tr = (tid / 16) * 8;
    int tc = (tid % 16) * 8;

    float acc[8][8];
#pragma unroll
    for (int i = 0; i < 8; i++)
#pragma unroll
        for (int j = 0; j < 8; j++) acc[i][j] = 0.f;

    int la_r = tid >> 1;            // 0..127
    int la_c = (tid & 1) * 8;       // 0 or 8
    int lb_r = tid >> 4;            // 0..15
    int lb_c = (tid & 15) * 8;      // 0..120

    float4 a0, a1, b0v, b1v;

    // tile loader into registers
    auto load_tile = [&](int k0) {
        int gm = m0 + la_r;
        if (gm < M) {
            const float* p = A + (size_t)gm * K + k0 + la_c;
            a0 = *(const float4*)p;
            a1 = *(const float4*)(p + 4);
        } else {
            a0 = make_float4(0.f, 0.f, 0.f, 0.f);
            a1 = a0;
        }
        int gn = n0 + lb_c;
        const float* q = B + (size_t)(k0 + lb_r) * N + gn;
        if (gn + 7 < N) {
            b0v = *(const float4*)q;
            b1v = *(const float4*)(q + 4);
        } else {
            float t[8];
#pragma unroll
            for (int j = 0; j < 8; j++) t[j] = (gn + j < N) ? q[j] : 0.f;
            b0v = make_float4(t[0], t[1], t[2], t[3]);
            b1v = make_float4(t[4], t[5], t[6], t[7]);
        }
    };
    auto store_tile = [&](int buf) {
        As[buf][la_c + 0][la_r] = a0.x; As[buf][la_c + 1][la_r] = a0.y;
        As[buf][la_c + 2][la_r] = a0.z; As[buf][la_c + 3][la_r] = a0.w;
        As[buf][la_c + 4][la_r] = a1.x; As[buf][la_c + 5][la_r] = a1.y;
        As[buf][la_c + 6][la_r] = a1.z; As[buf][la_c + 7][la_r] = a1.w;
        *(float4*)&Bs[buf][lb_r][lb_c] = b0v;
        *(float4*)&Bs[buf][lb_r][lb_c + 4] = b1v;
    };

    load_tile(0);
    store_tile(0);
    __syncthreads();

    int buf = 0;
    for (int k0 = 0; k0 < K; k0 += 16) {
        bool more = (k0 + 16) < K;
        if (more) load_tile(k0 + 16);       // global prefetch (overlaps compute)

#pragma unroll
        for (int kk = 0; kk < 16; kk++) {
            float4 av0 = *(const float4*)&As[buf][kk][tr];
            float4 av1 = *(const float4*)&As[buf][kk][tr + 4];
            float4 bv0 = *(const float4*)&Bs[buf][kk][tc];
            float4 bv1 = *(const float4*)&Bs[buf][kk][tc + 4];
            float a[8] = {av0.x, av0.y, av0.z, av0.w, av1.x, av1.y, av1.z, av1.w};
            float b[8] = {bv0.x, bv0.y, bv0.z, bv0.w, bv1.x, bv1.y, bv1.z, bv1.w};
#pragma unroll
            for (int i = 0; i < 8; i++)
#pragma unroll
                for (int j = 0; j < 8; j++)
                    acc[i][j] = fmaf(a[i], b[j], acc[i][j]);
        }

        if (more) {
            store_tile(buf ^ 1);
            __syncthreads();
            buf ^= 1;
        }
    }

#pragma unroll
    for (int i = 0; i < 8; i++) {
        int gm = m0 + tr + i;
        if (gm >= M) continue;
        size_t rowb = (size_t)gm * N;
#pragma unroll
        for (int j = 0; j < 8; j++) {
            int gn = n0 + tc + j;
            if (gn >= N) continue;
            float v = acc[i][j] + bias[gn];
            if (EPI == 1) v += res[rowb + gn];
            if (EPI == 2) v = v * normcdff(v);
            C[rowb + gn] = v;
        }
    }
}

// ---------------- im2col patch pack ----------------
__global__ __launch_bounds__(256) void pack_patches_k(const float* __restrict__ x)
{
    int row = blockIdx.x;               // b*576 + p
    int b = row / 576, p = row % 576;
    int gy = p / 24, gx = p % 24;
    float* out = g_patch + (size_t)row * DIMN;
    for (int k = threadIdx.x; k < DIMN; k += 256) {
        int c = k >> 8;
        int r = (k >> 4) & 15;
        int cc = k & 15;
        out[k] = x[(((size_t)(b * 3 + c) * 384) + gy * 16 + r) * 384 + gx * 16 + cc];
    }
}

// ---------------- 768x768 transpose of patch weight ----------------
__global__ void transpose_w_k(const float* __restrict__ W)
{
    __shared__ float t[32][33];
    int x = blockIdx.x * 32 + threadIdx.x;   // k
    int y = blockIdx.y * 32 + threadIdx.y;   // d
#pragma unroll
    for (int i = 0; i < 32; i += 8)
        t[threadIdx.y + i][threadIdx.x] = W[(size_t)(y + i) * DIMN + x];
    __syncthreads();
    int x2 = blockIdx.y * 32 + threadIdx.x;  // d
    int y2 = blockIdx.x * 32 + threadIdx.y;  // k
#pragma unroll
    for (int i = 0; i < 32; i += 8)
        g_wpt[(size_t)(y2 + i) * DIMN + x2] = t[threadIdx.x][threadIdx.y + i];
}

// ---------------- assemble h = concat(cls, patch_emb) + pos ----------------
__global__ __launch_bounds__(256) void assemble_k(
    const float* __restrict__ cls, const float* __restrict__ pos)
{
    int row = blockIdx.x;            // b*577 + n
    int b = row / NTOK, n = row % NTOK;
    float* out = g_h + (size_t)row * DIMN;
    const float* pe = g_y + (size_t)(b * 576 + n - 1) * DIMN;
    for (int d = threadIdx.x; d < DIMN; d += 256) {
        float v = (n == 0) ? cls[d] : pe[d];
        out[d] = v + pos[(size_t)n * DIMN + d];
    }
}

// ---------------- LayerNorm over 768 ----------------
__global__ __launch_bounds__(256) void layernorm_k(
    const float* __restrict__ in, size_t inStride,
    const float* __restrict__ gam, const float* __restrict__ bet,
    float* __restrict__ out, float eps)
{
    const float* p = in + (size_t)blockIdx.x * inStride;
    float* q = out + (size_t)blockIdx.x * DIMN;
    int tid = threadIdx.x;
    float x0 = p[tid], x1 = p[tid + 256], x2 = p[tid + 512];
    float s = x0 + x1 + x2;
    float ss = x0 * x0 + x1 * x1 + x2 * x2;
#pragma unroll
    for (int o = 16; o; o >>= 1) {
        s  += __shfl_xor_sync(0xffffffffu, s, o);
        ss += __shfl_xor_sync(0xffffffffu, ss, o);
    }
    __shared__ float sm[16];
    int wid = tid >> 5;
    if ((tid & 31) == 0) { sm[wid] = s; sm[8 + wid] = ss; }
    __syncthreads();
    s = 0.f; ss = 0.f;
#pragma unroll
    for (int w = 0; w < 8; w++) { s += sm[w]; ss += sm[8 + w]; }
    float mean = s * (1.f / 768.f);
    float var = ss * (1.f / 768.f) - mean * mean;
    float inv = rsqrtf(var + eps);
    q[tid]       = (x0 - mean) * inv * gam[tid]       + bet[tid];
    q[tid + 256] = (x1 - mean) * inv * gam[tid + 256] + bet[tid + 256];
    q[tid + 512] = (x2 - mean) * inv * gam[tid + 512] + bet[tid + 512];
}

// ---------------- attention: S = scale * Q K^T ----------------
__global__ __launch_bounds__(128) void attn_scores_k()
{
    __shared__ float Qs[32][68];
    __shared__ float Ks[128][68];
    int bh = blockIdx.z;
    int b = bh / NHEAD, h = bh % NHEAD;
    const float* qb = g_qkv + (size_t)b * NTOK * (3 * DIMN) + h * HDIM;
    const float* kb = qb + DIMN;
    int q0 = blockIdx.y * 32, k0 = blockIdx.x * 128;
    int tid = threadIdx.x;
    for (int t = tid; t < 32 * 16; t += 128) {
        int r = t >> 4, d = (t & 15) * 4, n = q0 + r;
        float4 v = make_float4(0.f, 0.f, 0.f, 0.f);
        if (n < NTOK) v = *(const float4*)(qb + (size_t)n * (3 * DIMN) + d);
        *(float4*)&Qs[r][d] = v;
    }
    for (int t = tid; t < 128 * 16; t += 128) {
        int r = t >> 4, d = (t & 15) * 4, n = k0 + r;
        float4 v = make_float4(0.f, 0.f, 0.f, 0.f);
        if (n < NTOK) v = *(const float4*)(kb + (size_t)n * (3 * DIMN) + d);
        *(float4*)&Ks[r][d] = v;
    }
    __syncthreads();

    int qt = (tid >> 4) * 4;    // 8 groups * 4 = 32
    int kt = (tid & 15) * 8;    // 16 * 8 = 128
    float acc[4][8];
#pragma unroll
    for (int i = 0; i < 4; i++)
#pragma unroll
        for (int j = 0; j < 8; j++) acc[i][j] = 0.f;

#pragma unroll 4
    for (int d = 0; d < HDIM; d += 4) {
        float4 qv[4], kv[8];
#pragma unroll
        for (int i = 0; i < 4; i++) qv[i] = *(const float4*)&Qs[qt + i][d];
#pragma unroll
        for (int j = 0; j < 8; j++) kv[j] = *(const float4*)&Ks[kt + j][d];
#pragma unroll
        for (int i = 0; i < 4; i++)
#pragma unroll
            for (int j = 0; j < 8; j++)
                acc[i][j] += qv[i].x * kv[j].x + qv[i].y * kv[j].y +
                             qv[i].z * kv[j].z + qv[i].w * kv[j].w;
    }

    float* Sb = g_att + (size_t)bh * NTOK * SPAD;
#pragma unroll
    for (int i = 0; i < 4; i++) {
        int q = q0 + qt + i;
        if (q >= NTOK) continue;
#pragma unroll
        for (int j = 0; j < 8; j++) {
            int k = k0 + kt + j;
            if (k >= NTOK) continue;
            Sb[(size_t)q * SPAD + k] = acc[i][j] * 0.125f;
        }
    }
}

// ---------------- row softmax over 577 (rows at stride SPAD) ----------------
__global__ __launch_bounds__(128) void softmax_k()
{
    float* p = g_att + (size_t)blockIdx.x * SPAD;
    int tid = threadIdx.x;
    __shared__ float sm[4];
    float m = -3.4e38f;
    for (int i = tid; i < NTOK; i += 128) m = fmaxf(m, p[i]);
#pragma unroll
    for (int o = 16; o; o >>= 1) m = fmaxf(m, __shfl_xor_sync(0xffffffffu, m, o));
    if ((tid & 31) == 0) sm[tid >> 5] = m;
    __syncthreads();
    m = fmaxf(fmaxf(sm[0], sm[1]), fmaxf(sm[2], sm[3]));

    float s = 0.f;
    for (int i = tid; i < NTOK; i += 128) {
        float e = __expf(p[i] - m);
        p[i] = e;
        s += e;
    }
#pragma unroll
    for (int o = 16; o; o >>= 1) s += __shfl_xor_sync(0xffffffffu, s, o);
    __syncthreads();
    if ((tid & 31) == 0) sm[tid >> 5] = s;
    __syncthreads();
    s = sm[0] + sm[1] + sm[2] + sm[3];
    float inv = 1.f / s;
    for (int i = tid; i < NTOK; i += 128) p[i] *= inv;
}

// ---------------- attention: O = S @ V, written to (B,N,H*HD) ----------------
// Padding columns [NTOK, SPAD) of g_att are never written (zero-initialized
// device global) and V smem rows >= NTOK are zeroed, so unguarded float4
// loads over the padded row are exact.
__global__ __launch_bounds__(128) void attn_av_k()
{
    __shared__ float Ss[64][68];
    __shared__ float Vs[64][68];
    int bh = blockIdx.y;
    int b = bh / NHEAD, h = bh % NHEAD;
    const float* Sb = g_att + (size_t)bh * NTOK * SPAD;
    const float* vb = g_qkv + (size_t)b * NTOK * (3 * DIMN) + h * HDIM + 2 * DIMN;
    int q0 = blockIdx.x * 64;
    int tid = threadIdx.x;
    int qt = (tid >> 3) * 4;     // 16 groups * 4 = 64
    int dt = (tid & 7) * 8;      // 8 * 8 = 64

    float acc[4][8];
#pragma unroll
    for (int i = 0; i < 4; i++)
#pragma unroll
        for (int j = 0; j < 8; j++) acc[i][j] = 0.f;

    for (int kc = 0; kc < NTOK; kc += 64) {
        __syncthreads();
        // S chunk: vectorized loads from padded rows
        for (int t = tid; t < 64 * 16; t += 128) {
            int r = t >> 4, c4 = (t & 15) * 4;
            int q = q0 + r;
            float4 v = make_float4(0.f, 0.f, 0.f, 0.f);
            if (q < NTOK) v = *(const float4*)(Sb + (size_t)q * SPAD + kc + c4);
            Ss[r][c4 + 0] = v.x; Ss[r][c4 + 1] = v.y;
            Ss[r][c4 + 2] = v.z; Ss[r][c4 + 3] = v.w;
        }
        for (int t = tid; t < 64 * 16; t += 128) {
            int r = t >> 4, c = (t & 15) * 4, n = kc + r;
            float4 v = make_float4(0.f, 0.f, 0.f, 0.f);
            if (n < NTOK) v = *(const float4*)(vb + (size_t)n * (3 * DIMN) + c);
            *(float4*)&Vs[r][c] = v;
        }
        __syncthreads();

#pragma unroll 8
        for (int k = 0; k < 64; k++) {
            float s0 = Ss[qt + 0][k];
            float s1 = Ss[qt + 1][k];
            float s2 = Ss[qt + 2][k];
            float s3 = Ss[qt + 3][k];
            float4 v0 = *(const float4*)&Vs[k][dt];
            float4 v1 = *(const float4*)&Vs[k][dt + 4];
            float vv[8] = {v0.x, v0.y, v0.z, v0.w, v1.x, v1.y, v1.z, v1.w};
#pragma unroll
            for (int j = 0; j < 8; j++) {
                acc[0][j] = fmaf(s0, vv[j], acc[0][j]);
                acc[1][j] = fmaf(s1, vv[j], acc[1][j]);
                acc[2][j] = fmaf(s2, vv[j], acc[2][j]);
                acc[3][j] = fmaf(s3, vv[j], acc[3][j]);
            }
        }
    }

#pragma unroll
    for (int i = 0; i < 4; i++) {
        int q = q0 + qt + i;
        if (q >= NTOK) continue;
        float* ob = g_o + ((size_t)(b * NTOK + q)) * DIMN + h * HDIM + dt;
#pragma unroll
        for (int j = 0; j < 8; j++) ob[j] = acc[i][j];
    }
}

// ---------------- classifier head ----------------
__global__ __launch_bounds__(256) void head_k(
    const float* __restrict__ W, const float* __restrict__ bias,
    float* __restrict__ out)
{
    __shared__ float cs[DIMN];
    int b = blockIdx.x;
    for (int k = threadIdx.x; k < DIMN; k += 256) cs[k] = g_cls[b * DIMN + k];
    __syncthreads();
    for (int n = threadIdx.x; n < NCLS; n += 256) {
        float s = bias[n];
        for (int k = 0; k < DIMN; k++) s = fmaf(cs[k], W[(size_t)k * NCLS + n], s);
        out[b * NCLS + n] = s;
    }
}

// ---------------- orchestration ----------------
extern "C" void kernel_launch(void* const* d_in, const int* in_sizes, int n_in,
                              void* d_out, int out_size)
{
    const float* x       = (const float*)d_in[0];
    const float* patch_w = (const float*)d_in[1];
    const float* patch_b = (const float*)d_in[2];
    const float* cls_t   = (const float*)d_in[3];
    const float* pos     = (const float*)d_in[4];
    const float* ln1_g   = (const float*)d_in[5];
    const float* ln1_b   = (const float*)d_in[6];
    const float* qkv_w   = (const float*)d_in[7];
    const float* qkv_b   = (const float*)d_in[8];
    const float* proj_w  = (const float*)d_in[9];
    const float* proj_b  = (const float*)d_in[10];
    const float* ln2_g   = (const float*)d_in[11];
    const float* ln2_b   = (const float*)d_in[12];
    const float* w1      = (const float*)d_in[13];
    const float* b1      = (const float*)d_in[14];
    const float* w2      = (const float*)d_in[15];
    const float* b2      = (const float*)d_in[16];
    const float* lnf_g   = (const float*)d_in[17];
    const float* lnf_b   = (const float*)d_in[18];
    const float* head_w  = (const float*)d_in[19];
    const float* head_b  = (const float*)d_in[20];
    float* out = (float*)d_out;

    float *ph, *py, *pq, *po, *pm, *pp, *pwt, *pc;
    cudaGetSymbolAddress((void**)&ph,  g_h);
    cudaGetSymbolAddress((void**)&py,  g_y);
    cudaGetSymbolAddress((void**)&pq,  g_qkv);
    cudaGetSymbolAddress((void**)&po,  g_o);
    cudaGetSymbolAddress((void**)&pm,  g_mid);
    cudaGetSymbolAddress((void**)&pp,  g_patch);
    cudaGetSymbolAddress((void**)&pwt, g_wpt);
    cudaGetSymbolAddress((void**)&pc,  g_cls);

    // patch embed
    pack_patches_k<<<PROWS, 256>>>(x);
    transpose_w_k<<<dim3(24, 24), dim3(32, 8)>>>(patch_w);
    sgemm_k<0><<<dim3(6, 36), 256>>>(pp, pwt, patch_b, nullptr, py,
                                     PROWS, DIMN, DIMN);
    assemble_k<<<ROWS, 256>>>(cls_t, pos);

    for (int l = 0; l < NDEPTH; l++) {
        const float* l1g = ln1_g + l * DIMN;
        const float* l1b = ln1_b + l * DIMN;
        const float* qw  = qkv_w + (size_t)l * DIMN * 3 * DIMN;
        const float* qb  = qkv_b + (size_t)l * 3 * DIMN;
        const float* pw  = proj_w + (size_t)l * DIMN * DIMN;
        const float* pb  = proj_b + (size_t)l * DIMN;
        const float* l2g = ln2_g + l * DIMN;
        const float* l2b = ln2_b + l * DIMN;
        const float* mw1 = w1 + (size_t)l * DIMN * HIDN;
        const float* mb1 = b1 + (size_t)l * HIDN;
        const float* mw2 = w2 + (size_t)l * HIDN * DIMN;
        const float* mb2 = b2 + (size_t)l * DIMN;

        layernorm_k<<<ROWS, 256>>>(ph, DIMN, l1g, l1b, py, 1e-5f);
        sgemm_k<0><<<dim3(18, 37), 256>>>(py, qw, qb, nullptr, pq,
                                          ROWS, 3 * DIMN, DIMN);
        attn_scores_k<<<dim3(5, 19, BATCH * NHEAD), 128>>>();
        softmax_k<<<BATCH * NHEAD * NTOK, 128>>>();
        attn_av_k<<<dim3(10, BATCH * NHEAD), 128>>>();
        sgemm_k<1><<<dim3(6, 37), 256>>>(po, pw, pb, ph, ph,
                                         ROWS, DIMN, DIMN);
        layernorm_k<<<ROWS, 256>>>(ph, DIMN, l2g, l2b, py, 1e-5f);
        sgemm_k<2><<<dim3(24, 37), 256>>>(py, mw1, mb1, nullptr, pm,
                                          ROWS, HIDN, DIMN);
        sgemm_k<1><<<dim3(6, 37), 256>>>(pm, mw2, mb2, ph, ph,
                                         ROWS, DIMN, HIDN);
    }

    layernorm_k<<<BATCH, 256>>>(ph, (size_t)NTOK * DIMN, lnf_g, lnf_b, pc, 1e-6f);
    head_k<<<BATCH, 256>>>(head_w, head_b, out);
}

// round 8
// speedup vs baseline: 1.6660x; 1.6660x over previous
#include <cuda_runtime.h>
#include <cuda_bf16.h>
#include <math.h>
#include <stdint.h>

#define NDEPTH 12
#define DIMN   768
#define NHEAD  12
#define HDIM   64
#define NTOK   577
#define NCLS   1000
#define HIDN   3072
#define BATCH  8
#define ROWS   (BATCH * NTOK)   // 4616
#define PROWS  (BATCH * 576)    // 4608
#define SPAD   640              // padded attention row stride

// single-layer transposed-weight element counts / offsets
#define WL_TOTAL 7077888u       // qkv(2304*768) + proj(768*768) + w1(3072*768) + w2(768*3072)
#define WOFF_QKV  0u
#define WOFF_PROJ 1769472u
#define WOFF_W1   2359296u
#define WOFF_W2   4718592u

// ---------------- scratch (static device memory; no allocations) ----------------
__device__ __align__(256) float g_patch[PROWS * DIMN];
__device__ __align__(256) float g_h[ROWS * DIMN];
__device__ __align__(256) float g_y[PROWS * DIMN];
__device__ __align__(256) float g_qkv[ROWS * 3 * DIMN];
__device__ __align__(256) float g_att[(size_t)BATCH * NHEAD * NTOK * SPAD];
__device__ __align__(256) float g_wpt[DIMN * DIMN];
__device__ __align__(256) float g_cls[BATCH * DIMN];

// bf16 hi/lo activation splits
__device__ __align__(256) __nv_bfloat16 g_yh[ROWS * DIMN];
__device__ __align__(256) __nv_bfloat16 g_yl[ROWS * DIMN];
__device__ __align__(256) __nv_bfloat16 g_oh[ROWS * DIMN];
__device__ __align__(256) __nv_bfloat16 g_ol[ROWS * DIMN];
__device__ __align__(256) __nv_bfloat16 g_mh[(size_t)ROWS * HIDN];
__device__ __align__(256) __nv_bfloat16 g_ml[(size_t)ROWS * HIDN];

// bf16 hi/lo transposed weights, ONE layer at a time (split runs per-layer in-graph)
__device__ __align__(256) __nv_bfloat16 g_wth[WL_TOTAL];
__device__ __align__(256) __nv_bfloat16 g_wtl[WL_TOTAL];

// ---------------- helpers ----------------
__device__ __forceinline__ uint32_t smem_u32(const void* p) {
    uint32_t a;
    asm("{ .reg .u64 t; cvta.to.shared.u64 t, %1; cvt.u32.u64 %0, t; }" : "=r"(a) : "l"(p));
    return a;
}
__device__ __forceinline__ void cp16(uint32_t dst, const void* src) {
    asm volatile("cp.async.cg.shared.global [%0], [%1], 16;" :: "r"(dst), "l"(src) : "memory");
}
#define CP_COMMIT() asm volatile("cp.async.commit_group;" ::: "memory")
#define CP_WAIT(n)  asm volatile("cp.async.wait_group %0;" :: "n"(n) : "memory")

__device__ __forceinline__ void ldsm4(uint32_t& r0, uint32_t& r1, uint32_t& r2, uint32_t& r3,
                                      uint32_t addr) {
    asm volatile("ldmatrix.sync.aligned.m8n8.x4.shared.b16 {%0,%1,%2,%3}, [%4];"
                 : "=r"(r0), "=r"(r1), "=r"(r2), "=r"(r3) : "r"(addr));
}
__device__ __forceinline__ void mma16816(float* c, uint32_t a0, uint32_t a1, uint32_t a2,
                                         uint32_t a3, uint32_t b0, uint32_t b1) {
    asm volatile(
        "mma.sync.aligned.m16n8k16.row.col.f32.bf16.bf16.f32 "
        "{%0,%1,%2,%3}, {%4,%5,%6,%7}, {%8,%9}, {%0,%1,%2,%3};"
        : "+f"(c[0]), "+f"(c[1]), "+f"(c[2]), "+f"(c[3])
        : "r"(a0), "r"(a1), "r"(a2), "r"(a3), "r"(b0), "r"(b1));
}
__device__ __forceinline__ void split2(float v, __nv_bfloat16& h, __nv_bfloat16& l) {
    h = __float2bfloat16_rn(v);
    l = __float2bfloat16_rn(v - __bfloat162float(h));
}

// smem stage layout (bytes): A_hi | A_lo | B_hi | B_lo, rows padded to 80 B
#define RSB      80
#define OFF_ALO  10240
#define OFF_BHI  20480
#define OFF_BLO  30720
#define STAGE    40960
#define WG_SMEM  (2 * STAGE)     // 81920

// ================= warp-mma split-bf16 GEMM =================
// D[M,N] = (A_hi+A_lo)[M,K] @ (B_hi+B_lo)^T,  B stored [N][K] K-major.
// EPI 0: C=acc+bias (fp32)  1: +res  2: gelu -> bf16 hi/lo
// RACE-FIX (R7): prefetch of stage c+2 (which reuses buffer c&1) is issued
// AFTER the compute on buffer c&1 and its closing __syncthreads. Stage c+1
// remains in flight during compute of c, so the pipeline depth is unchanged.
template <int EPI>
__global__ __launch_bounds__(256) void wgemm_k(
    const __nv_bfloat16* __restrict__ a_hi, const __nv_bfloat16* __restrict__ a_lo,
    const __nv_bfloat16* __restrict__ b_hi, const __nv_bfloat16* __restrict__ b_lo,
    const float* __restrict__ bias, const float* __restrict__ res,
    float* __restrict__ Cf, __nv_bfloat16* __restrict__ Ch, __nv_bfloat16* __restrict__ Cl,
    int M, int N, int K)
{
    extern __shared__ __align__(16) char smem[];
    uint32_t sb0 = smem_u32(smem);
    int tid = threadIdx.x;
    int wid = tid >> 5, lane = tid & 31;
    int warp_m = wid & 3;          // 4 warps along M, 32 rows each
    int warp_n = wid >> 2;         // 2 warps along N, 64 cols each
    int m0 = blockIdx.y * 128;
    int n0 = blockIdx.x * 128;

    float acc[2][8][4];
#pragma unroll
    for (int i = 0; i < 2; i++)
#pragma unroll
        for (int j = 0; j < 8; j++)
#pragma unroll
            for (int q = 0; q < 4; q++) acc[i][j][q] = 0.f;

    int C = K >> 5;                 // chunks of 32

    auto load_stage = [&](int c) {
        uint32_t base = sb0 + (c & 1) * STAGE;
        int k0 = c * 32;
#pragma unroll
        for (int j = 0; j < 2; j++) {
            int seg = tid + 256 * j;        // 0..511
            int row = seg >> 2, c8 = seg & 3;
            int gm = m0 + row; if (gm >= M) gm = M - 1;
            size_t sa = (size_t)gm * K + k0 + c8 * 8;
            uint32_t da = base + row * RSB + c8 * 16;
            cp16(da, a_hi + sa);
            cp16(da + OFF_ALO, a_lo + sa);
            size_t sn = (size_t)(n0 + row) * K + k0 + c8 * 8;
            uint32_t db = base + OFF_BHI + row * RSB + c8 * 16;
            cp16(db, b_hi + sn);
            cp16(db + (OFF_BLO - OFF_BHI), b_lo + sn);
        }
        CP_COMMIT();
    };

    load_stage(0);
    if (C > 1) load_stage(1);

    int lr = lane & 15;             // ldmatrix row selector
    int lc = (lane >> 4) * 16;      // 0 or 16 bytes (k half)

    for (int c = 0; c < C; c++) {
        if (c + 1 < C) CP_WAIT(1); else CP_WAIT(0);
        __syncthreads();

        uint32_t base = sb0 + (c & 1) * STAGE;
        uint32_t a_row = base + (warp_m * 32 + lr) * RSB + lc;
        uint32_t b_row = base + OFF_BHI + (warp_n * 64 + lr) * RSB + lc;

#pragma unroll
        for (int kk = 0; kk < 2; kk++) {
            uint32_t koff = kk * 32;   // 16 halves
            uint32_t ah[2][4], al[2][4];
#pragma unroll
            for (int mf = 0; mf < 2; mf++) {
                uint32_t addr = a_row + mf * 16 * RSB + koff;
                ldsm4(ah[mf][0], ah[mf][1], ah[mf][2], ah[mf][3], addr);
                ldsm4(al[mf][0], al[mf][1], al[mf][2], al[mf][3], addr + OFF_ALO);
            }
#pragma unroll
            for (int pr = 0; pr < 4; pr++) {
                uint32_t addr = b_row + pr * 16 * RSB + koff;
                uint32_t bh0, bh1, bh2, bh3, bl0, bl1, bl2, bl3;
                ldsm4(bh0, bh1, bh2, bh3, addr);
                ldsm4(bl0, bl1, bl2, bl3, addr + (OFF_BLO - OFF_BHI));
#pragma unroll
                for (int mf = 0; mf < 2; mf++) {
                    mma16816(acc[mf][2 * pr],     ah[mf][0], ah[mf][1], ah[mf][2], ah[mf][3], bh0, bh2);
                    mma16816(acc[mf][2 * pr],     ah[mf][0], ah[mf][1], ah[mf][2], ah[mf][3], bl0, bl2);
                    mma16816(acc[mf][2 * pr],     al[mf][0], al[mf][1], al[mf][2], al[mf][3], bh0, bh2);
                    mma16816(acc[mf][2 * pr + 1], ah[mf][0], ah[mf][1], ah[mf][2], ah[mf][3], bh1, bh3);
                    mma16816(acc[mf][2 * pr + 1], ah[mf][0], ah[mf][1], ah[mf][2], ah[mf][3], bl1, bl3);
                    mma16816(acc[mf][2 * pr + 1], al[mf][0], al[mf][1], al[mf][2], al[mf][3], bh1, bh3);
                }
            }
        }
        __syncthreads();
        if (c + 2 < C) load_stage(c + 2);   // safe: all reads of buffer c&1 done
    }

    // epilogue
    int rbase = m0 + warp_m * 32 + (lane >> 2);
    int cbase = n0 + warp_n * 64 + (lane & 3) * 2;
#pragma unroll
    for (int mf = 0; mf < 2; mf++) {
#pragma unroll
        for (int nf = 0; nf < 8; nf++) {
            int n = cbase + nf * 8;
            float b0 = bias[n], b1 = bias[n + 1];
#pragma unroll
            for (int half = 0; half < 2; half++) {
                int m = rbase + mf * 16 + half * 8;
                if (m >= M) continue;
                float v0 = acc[mf][nf][2 * half]     + b0;
                float v1 = acc[mf][nf][2 * half + 1] + b1;
                size_t o = (size_t)m * N + n;
                if (EPI == 2) {
                    v0 = v0 * normcdff(v0);
                    v1 = v1 * normcdff(v1);
                    __nv_bfloat16 h0, l0, h1, l1;
                    split2(v0, h0, l0); split2(v1, h1, l1);
                    *(__nv_bfloat162*)&Ch[o] = __nv_bfloat162(h0, h1);
                    *(__nv_bfloat162*)&Cl[o] = __nv_bfloat162(l0, l1);
                } else {
                    if (EPI == 1) {
                        float2 rv = *(const float2*)&res[o];
                        v0 += rv.x; v1 += rv.y;
                    }
                    *(float2*)&Cf[o] = make_float2(v0, v1);
                }
            }
        }
    }
}

// ================= weight transpose + bf16 split =================
__global__ void tsplit_k(const float* __restrict__ W,
                         __nv_bfloat16* __restrict__ oh, __nv_bfloat16* __restrict__ ol,
                         int K, int N)
{
    __shared__ float t[32][33];
    int x = blockIdx.x * 32 + threadIdx.x;   // n
    int y = blockIdx.y * 32 + threadIdx.y;   // k
#pragma unroll
    for (int i = 0; i < 32; i += 8)
        t[threadIdx.y + i][threadIdx.x] = W[(size_t)(y + i) * N + x];
    __syncthreads();
    int n = blockIdx.x * 32 + threadIdx.y;
    int k = blockIdx.y * 32 + threadIdx.x;
#pragma unroll
    for (int i = 0; i < 32; i += 8) {
        float v = t[threadIdx.x][threadIdx.y + i];
        __nv_bfloat16 h, l;
        split2(v, h, l);
        oh[(size_t)(n + i) * K + k] = h;
        ol[(size_t)(n + i) * K + k] = l;
    }
}

// ---------------- fp32 SGEMM for patch embed only ----------------
__global__ __launch_bounds__(256) void sgemm_patch(
    const float* __restrict__ A, const float* __restrict__ B,
    const float* __restrict__ bias, float* __restrict__ C, int M, int N, int K)
{
    __shared__ float As[2][16][128];
    __shared__ float Bs[2][16][128];
    int tid = threadIdx.x;
    int m0 = blockIdx.y * 128, n0 = blockIdx.x * 128;
    int tr = (tid / 16) * 8, tc = (tid % 16) * 8;
    float acc[8][8];
#pragma unroll
    for (int i = 0; i < 8; i++)
#pragma unroll
        for (int j = 0; j < 8; j++) acc[i][j] = 0.f;
    int la_r = tid >> 1, la_c = (tid & 1) * 8;
    int lb_r = tid >> 4, lb_c = (tid & 15) * 8;
    float4 a0, a1, b0v, b1v;
    auto load_tile = [&](int k0) {
        int gm = m0 + la_r;
        if (gm < M) {
            const float* p = A + (size_t)gm * K + k0 + la_c;
            a0 = *(const float4*)p; a1 = *(const float4*)(p + 4);
        } else { a0 = make_float4(0.f,0.f,0.f,0.f); a1 = a0; }
        const float* q = B + (size_t)(k0 + lb_r) * N + n0 + lb_c;
        b0v = *(const float4*)q; b1v = *(const float4*)(q + 4);
    };
    auto store_tile = [&](int buf) {
        As[buf][la_c+0][la_r]=a0.x; As[buf][la_c+1][la_r]=a0.y;
        As[buf][la_c+2][la_r]=a0.z; As[buf][la_c+3][la_r]=a0.w;
        As[buf][la_c+4][la_r]=a1.x; As[buf][la_c+5][la_r]=a1.y;
        As[buf][la_c+6][la_r]=a1.z; As[buf][la_c+7][la_r]=a1.w;
        *(float4*)&Bs[buf][lb_r][lb_c] = b0v;
        *(float4*)&Bs[buf][lb_r][lb_c+4] = b1v;
    };
    load_tile(0); store_tile(0); __syncthreads();
    int buf = 0;
    for (int k0 = 0; k0 < K; k0 += 16) {
        bool more = (k0 + 16) < K;
        if (more) load_tile(k0 + 16);
#pragma unroll
        for (int kk = 0; kk < 16; kk++) {
            float4 av0 = *(const float4*)&As[buf][kk][tr];
            float4 av1 = *(const float4*)&As[buf][kk][tr+4];
            float4 bv0 = *(const float4*)&Bs[buf][kk][tc];
            float4 bv1 = *(const float4*)&Bs[buf][kk][tc+4];
            float a[8] = {av0.x,av0.y,av0.z,av0.w,av1.x,av1.y,av1.z,av1.w};
            float b[8] = {bv0.x,bv0.y,bv0.z,bv0.w,bv1.x,bv1.y,bv1.z,bv1.w};
#pragma unroll
            for (int i = 0; i < 8; i++)
#pragma unroll
                for (int j = 0; j < 8; j++)
                    acc[i][j] = fmaf(a[i], b[j], acc[i][j]);
        }
        if (more) { store_tile(buf ^ 1); __syncthreads(); buf ^= 1; }
    }
#pragma unroll
    for (int i = 0; i < 8; i++) {
        int gm = m0 + tr + i;
        if (gm >= M) continue;
        size_t rowb = (size_t)gm * N;
#pragma unroll
        for (int j = 0; j < 8; j++) {
            int gn = n0 + tc + j;
            C[rowb + gn] = acc[i][j] + bias[gn];
        }
    }
}

// ---------------- im2col patch pack ----------------
__global__ __launch_bounds__(256) void pack_patches_k(const float* __restrict__ x)
{
    int row = blockIdx.x;
    int b = row / 576, p = row % 576;
    int gy = p / 24, gx = p % 24;
    float* out = g_patch + (size_t)row * DIMN;
    for (int k = threadIdx.x; k < DIMN; k += 256) {
        int c = k >> 8, r = (k >> 4) & 15, cc = k & 15;
        out[k] = x[(((size_t)(b * 3 + c) * 384) + gy * 16 + r) * 384 + gx * 16 + cc];
    }
}

__global__ void transpose_w_k(const float* __restrict__ W)
{
    __shared__ float t[32][33];
    int x = blockIdx.x * 32 + threadIdx.x;
    int y = blockIdx.y * 32 + threadIdx.y;
#pragma unroll
    for (int i = 0; i < 32; i += 8)
        t[threadIdx.y + i][threadIdx.x] = W[(size_t)(y + i) * DIMN + x];
    __syncthreads();
    int x2 = blockIdx.y * 32 + threadIdx.x;
    int y2 = blockIdx.x * 32 + threadIdx.y;
#pragma unroll
    for (int i = 0; i < 32; i += 8)
        g_wpt[(size_t)(y2 + i) * DIMN + x2] = t[threadIdx.x][threadIdx.y + i];
}

__global__ __launch_bounds__(256) void assemble_k(
    const float* __restrict__ cls, const float* __restrict__ pos)
{
    int row = blockIdx.x;
    int b = row / NTOK, n = row % NTOK;
    float* out = g_h + (size_t)row * DIMN;
    const float* pe = g_y + (size_t)(b * 576 + n - 1) * DIMN;
    for (int d = threadIdx.x; d < DIMN; d += 256) {
        float v = (n == 0) ? cls[d] : pe[d];
        out[d] = v + pos[(size_t)n * DIMN + d];
    }
}

// ---------------- LayerNorm -> bf16 hi/lo split ----------------
__global__ __launch_bounds__(256) void layernorm_split_k(
    const float* __restrict__ in,
    const float* __restrict__ gam, const float* __restrict__ bet,
    __nv_bfloat16* __restrict__ oh, __nv_bfloat16* __restrict__ ol)
{
    const float* p = in + (size_t)blockIdx.x * DIMN;
    size_t rowb = (size_t)blockIdx.x * DIMN;
    int tid = threadIdx.x;
    float x0 = p[tid], x1 = p[tid + 256], x2 = p[tid + 512];
    float s = x0 + x1 + x2;
    float ss = x0*x0 + x1*x1 + x2*x2;
#pragma unroll
    for (int o = 16; o; o >>= 1) {
        s  += __shfl_xor_sync(0xffffffffu, s, o);
        ss += __shfl_xor_sync(0xffffffffu, ss, o);
    }
    __shared__ float sm[16];
    int wid = tid >> 5;
    if ((tid & 31) == 0) { sm[wid] = s; sm[8 + wid] = ss; }
    __syncthreads();
    s = 0.f; ss = 0.f;
#pragma unroll
    for (int w = 0; w < 8; w++) { s += sm[w]; ss += sm[8 + w]; }
    float mean = s * (1.f / 768.f);
    float var = ss * (1.f / 768.f) - mean * mean;
    float inv = rsqrtf(var + 1e-5f);
#pragma unroll
    for (int q = 0; q < 3; q++) {
        int d = tid + q * 256;
        float v = (q == 0 ? x0 : q == 1 ? x1 : x2);
        v = (v - mean) * inv * gam[d] + bet[d];
        __nv_bfloat16 h, l;
        split2(v, h, l);
        oh[rowb + d] = h;
        ol[rowb + d] = l;
    }
}

// ---------------- final LayerNorm (fp32 out) ----------------
__global__ __launch_bounds__(256) void layernorm_k(
    const float* __restrict__ in, size_t inStride,
    const float* __restrict__ gam, const float* __restrict__ bet,
    float* __restrict__ out, float eps)
{
    const float* p = in + (size_t)blockIdx.x * inStride;
    float* q = out + (size_t)blockIdx.x * DIMN;
    int tid = threadIdx.x;
    float x0 = p[tid], x1 = p[tid + 256], x2 = p[tid + 512];
    float s = x0 + x1 + x2;
    float ss = x0*x0 + x1*x1 + x2*x2;
#pragma unroll
    for (int o = 16; o; o >>= 1) {
        s  += __shfl_xor_sync(0xffffffffu, s, o);
        ss += __shfl_xor_sync(0xffffffffu, ss, o);
    }
    __shared__ float sm[16];
    int wid = tid >> 5;
    if ((tid & 31) == 0) { sm[wid] = s; sm[8 + wid] = ss; }
    __syncthreads();
    s = 0.f; ss = 0.f;
#pragma unroll
    for (int w = 0; w < 8; w++) { s += sm[w]; ss += sm[8 + w]; }
    float mean = s * (1.f / 768.f);
    float var = ss * (1.f / 768.f) - mean * mean;
    float inv = rsqrtf(var + eps);
    q[tid]       = (x0 - mean) * inv * gam[tid]       + bet[tid];
    q[tid + 256] = (x1 - mean) * inv * gam[tid + 256] + bet[tid + 256];
    q[tid + 512] = (x2 - mean) * inv * gam[tid + 512] + bet[tid + 512];
}

// ---------------- attention: S = scale * Q K^T ----------------
__global__ __launch_bounds__(128) void attn_scores_k()
{
    __shared__ float Qs[32][68];
    __shared__ float Ks[128][68];
    int bh = blockIdx.z;
    int b = bh / NHEAD, h = bh % NHEAD;
    const float* qb = g_qkv + (size_t)b * NTOK * (3 * DIMN) + h * HDIM;
    const float* kb = qb + DIMN;
    int q0 = blockIdx.y * 32, k0 = blockIdx.x * 128;
    int tid = threadIdx.x;
    for (int t = tid; t < 32 * 16; t += 128) {
        int r = t >> 4, d = (t & 15) * 4, n = q0 + r;
        float4 v = make_float4(0.f, 0.f, 0.f, 0.f);
        if (n < NTOK) v = *(const float4*)(qb + (size_t)n * (3 * DIMN) + d);
        *(float4*)&Qs[r][d] = v;
    }
    for (int t = tid; t < 128 * 16; t += 128) {
        int r = t >> 4, d = (t & 15) * 4, n = k0 + r;
        float4 v = make_float4(0.f, 0.f, 0.f, 0.f);
        if (n < NTOK) v = *(const float4*)(kb + (size_t)n * (3 * DIMN) + d);
        *(float4*)&Ks[r][d] = v;
    }
    __syncthreads();
    int qt = (tid >> 4) * 4, kt = (tid & 15) * 8;
    float acc[4][8];
#pragma unroll
    for (int i = 0; i < 4; i++)
#pragma unroll
        for (int j = 0; j < 8; j++) acc[i][j] = 0.f;
#pragma unroll 4
    for (int d = 0; d < HDIM; d += 4) {
        float4 qv[4], kv[8];
#pragma unroll
        for (int i = 0; i < 4; i++) qv[i] = *(const float4*)&Qs[qt + i][d];
#pragma unroll
        for (int j = 0; j < 8; j++) kv[j] = *(const float4*)&Ks[kt + j][d];
#pragma unroll
        for (int i = 0; i < 4; i++)
#pragma unroll
            for (int j = 0; j < 8; j++)
                acc[i][j] += qv[i].x*kv[j].x + qv[i].y*kv[j].y +
                             qv[i].z*kv[j].z + qv[i].w*kv[j].w;
    }
    float* Sb = g_att + (size_t)bh * NTOK * SPAD;
#pragma unroll
    for (int i = 0; i < 4; i++) {
        int q = q0 + qt + i;
        if (q >= NTOK) continue;
#pragma unroll
        for (int j = 0; j < 8; j++) {
            int k = k0 + kt + j;
            if (k >= NTOK) continue;
            Sb[(size_t)q * SPAD + k] = acc[i][j] * 0.125f;
        }
    }
}

// ---------------- row softmax ----------------
__global__ __launch_bounds__(128) void softmax_k()
{
    float* p = g_att + (size_t)blockIdx.x * SPAD;
    int tid = threadIdx.x;
    __shared__ float sm[4];
    float m = -3.4e38f;
    for (int i = tid; i < NTOK; i += 128) m = fmaxf(m, p[i]);
#pragma unroll
    for (int o = 16; o; o >>= 1) m = fmaxf(m, __shfl_xor_sync(0xffffffffu, m, o));
    if ((tid & 31) == 0) sm[tid >> 5] = m;
    __syncthreads();
    m = fmaxf(fmaxf(sm[0], sm[1]), fmaxf(sm[2], sm[3]));
    float s = 0.f;
    for (int i = tid; i < NTOK; i += 128) {
        float e = __expf(p[i] - m);
        p[i] = e;
        s += e;
    }
#pragma unroll
    for (int o = 16; o; o >>= 1) s += __shfl_xor_sync(0xffffffffu, s, o);
    __syncthreads();
    if ((tid & 31) == 0) sm[tid >> 5] = s;
    __syncthreads();
    s = sm[0] + sm[1] + sm[2] + sm[3];
    float inv = 1.f / s;
    for (int i = tid; i < NTOK; i += 128) p[i] *= inv;
}

// ---------------- attention: O = S @ V -> bf16 hi/lo ----------------
__global__ __launch_bounds__(128) void attn_av_k()
{
    __shared__ float Ss[64][68];
    __shared__ float Vs[64][68];
    int bh = blockIdx.y;
    int b = bh / NHEAD, h = bh % NHEAD;
    const float* Sb = g_att + (size_t)bh * NTOK * SPAD;
    const float* vb = g_qkv + (size_t)b * NTOK * (3 * DIMN) + h * HDIM + 2 * DIMN;
    int q0 = blockIdx.x * 64;
    int tid = threadIdx.x;
    int qt = (tid >> 3) * 4, dt = (tid & 7) * 8;
    float acc[4][8];
#pragma unroll
    for (int i = 0; i < 4; i++)
#pragma unroll
        for (int j = 0; j < 8; j++) acc[i][j] = 0.f;

    for (int kc = 0; kc < NTOK; kc += 64) {
        __syncthreads();
        for (int t = tid; t < 64 * 16; t += 128) {
            int r = t >> 4, c4 = (t & 15) * 4;
            int q = q0 + r;
            float4 v = make_float4(0.f, 0.f, 0.f, 0.f);
            if (q < NTOK) v = *(const float4*)(Sb + (size_t)q * SPAD + kc + c4);
            Ss[r][c4+0]=v.x; Ss[r][c4+1]=v.y; Ss[r][c4+2]=v.z; Ss[r][c4+3]=v.w;
        }
        for (int t = tid; t < 64 * 16; t += 128) {
            int r = t >> 4, c = (t & 15) * 4, n = kc + r;
            float4 v = make_float4(0.f, 0.f, 0.f, 0.f);
            if (n < NTOK) v = *(const float4*)(vb + (size_t)n * (3 * DIMN) + c);
            *(float4*)&Vs[r][c] = v;
        }
        __syncthreads();
#pragma unroll 8
        for (int k = 0; k < 64; k++) {
            float s0 = Ss[qt+0][k], s1 = Ss[qt+1][k], s2 = Ss[qt+2][k], s3 = Ss[qt+3][k];
            float4 v0 = *(const float4*)&Vs[k][dt];
            float4 v1 = *(const float4*)&Vs[k][dt+4];
            float vv[8] = {v0.x,v0.y,v0.z,v0.w,v1.x,v1.y,v1.z,v1.w};
#pragma unroll
            for (int j = 0; j < 8; j++) {
                acc[0][j] = fmaf(s0, vv[j], acc[0][j]);
                acc[1][j] = fmaf(s1, vv[j], acc[1][j]);
                acc[2][j] = fmaf(s2, vv[j], acc[2][j]);
                acc[3][j] = fmaf(s3, vv[j], acc[3][j]);
            }
        }
    }
#pragma unroll
    for (int i = 0; i < 4; i++) {
        int q = q0 + qt + i;
        if (q >= NTOK) continue;
        size_t ob = ((size_t)(b * NTOK + q)) * DIMN + h * HDIM + dt;
#pragma unroll
        for (int j = 0; j < 8; j++) {
            __nv_bfloat16 hh, ll;
            split2(acc[i][j], hh, ll);
            g_oh[ob + j] = hh;
            g_ol[ob + j] = ll;
        }
    }
}

// ---------------- classifier head ----------------
__global__ __launch_bounds__(256) void head_k(
    const float* __restrict__ W, const float* __restrict__ bias,
    float* __restrict__ out)
{
    __shared__ float cs[DIMN];
    int b = blockIdx.x;
    for (int k = threadIdx.x; k < DIMN; k += 256) cs[k] = g_cls[b * DIMN + k];
    __syncthreads();
    for (int n = threadIdx.x; n < NCLS; n += 256) {
        float s = bias[n];
        for (int k = 0; k < DIMN; k++) s = fmaf(cs[k], W[(size_t)k * NCLS + n], s);
        out[b * NCLS + n] = s;
    }
}

// ---------------- orchestration ----------------
extern "C" void kernel_launch(void* const* d_in, const int* in_sizes, int n_in,
                              void* d_out, int out_size)
{
    const float* x       = (const float*)d_in[0];
    const float* patch_w = (const float*)d_in[1];
    const float* patch_b = (const float*)d_in[2];
    const float* cls_t   = (const float*)d_in[3];
    const float* pos     = (const float*)d_in[4];
    const float* ln1_g   = (const float*)d_in[5];
    const float* ln1_b   = (const float*)d_in[6];
    const float* qkv_w   = (const float*)d_in[7];
    const float* qkv_b   = (const float*)d_in[8];
    const float* proj_w  = (const float*)d_in[9];
    const float* proj_b  = (const float*)d_in[10];
    const float* ln2_g   = (const float*)d_in[11];
    const float* ln2_b   = (const float*)d_in[12];
    const float* w1      = (const float*)d_in[13];
    const float* b1      = (const float*)d_in[14];
    const float* w2      = (const float*)d_in[15];
    const float* b2      = (const float*)d_in[16];
    const float* lnf_g   = (const float*)d_in[17];
    const float* lnf_b   = (const float*)d_in[18];
    const float* head_w  = (const float*)d_in[19];
    const float* head_b  = (const float*)d_in[20];
    float* out = (float*)d_out;

    float *ph, *py, *pq, *pp, *pwt, *pc;
    __nv_bfloat16 *pyh, *pyl, *poh, *pol, *pmh, *pml, *pwh, *pwl;
    cudaGetSymbolAddress((void**)&ph,  g_h);
    cudaGetSymbolAddress((void**)&py,  g_y);
    cudaGetSymbolAddress((void**)&pq,  g_qkv);
    cudaGetSymbolAddress((void**)&pp,  g_patch);
    cudaGetSymbolAddress((void**)&pwt, g_wpt);
    cudaGetSymbolAddress((void**)&pc,  g_cls);
    cudaGetSymbolAddress((void**)&pyh, g_yh);
    cudaGetSymbolAddress((void**)&pyl, g_yl);
    cudaGetSymbolAddress((void**)&poh, g_oh);
    cudaGetSymbolAddress((void**)&pol, g_ol);
    cudaGetSymbolAddress((void**)&pmh, g_mh);
    cudaGetSymbolAddress((void**)&pml, g_ml);
    cudaGetSymbolAddress((void**)&pwh, g_wth);
    cudaGetSymbolAddress((void**)&pwl, g_wtl);

    cudaFuncSetAttribute(wgemm_k<0>, cudaFuncAttributeMaxDynamicSharedMemorySize, WG_SMEM);
    cudaFuncSetAttribute(wgemm_k<1>, cudaFuncAttributeMaxDynamicSharedMemorySize, WG_SMEM);
    cudaFuncSetAttribute(wgemm_k<2>, cudaFuncAttributeMaxDynamicSharedMemorySize, WG_SMEM);

    // ---- patch embed (fp32) ----
    pack_patches_k<<<PROWS, 256>>>(x);
    transpose_w_k<<<dim3(24, 24), dim3(32, 8)>>>(patch_w);
    sgemm_patch<<<dim3(6, 36), 256>>>(pp, pwt, patch_b, py, PROWS, DIMN, DIMN);
    assemble_k<<<ROWS, 256>>>(cls_t, pos);

    int mt = (ROWS + 127) / 128;   // 37
    for (int l = 0; l < NDEPTH; l++) {
        const float* l1g = ln1_g + l * DIMN;
        const float* l1b = ln1_b + l * DIMN;
        const float* qb  = qkv_b + (size_t)l * 3 * DIMN;
        const float* pb  = proj_b + (size_t)l * DIMN;
        const float* l2g = ln2_g + l * DIMN;
        const float* l2b = ln2_b + l * DIMN;
        const float* mb1 = b1 + (size_t)l * HIDN;
        const float* mb2 = b2 + (size_t)l * DIMN;

        // split this layer's weights into the single-layer buffer (in-graph, per replay)
        tsplit_k<<<dim3(2304/32, 768/32), dim3(32, 8)>>>(
            qkv_w + (size_t)l * DIMN * 3 * DIMN, pwh + WOFF_QKV, pwl + WOFF_QKV, 768, 2304);
        tsplit_k<<<dim3(768/32, 768/32), dim3(32, 8)>>>(
            proj_w + (size_t)l * DIMN * DIMN, pwh + WOFF_PROJ, pwl + WOFF_PROJ, 768, 768);
        tsplit_k<<<dim3(3072/32, 768/32), dim3(32, 8)>>>(
            w1 + (size_t)l * DIMN * HIDN, pwh + WOFF_W1, pwl + WOFF_W1, 768, 3072);
        tsplit_k<<<dim3(768/32, 3072/32), dim3(32, 8)>>>(
            w2 + (size_t)l * HIDN * DIMN, pwh + WOFF_W2, pwl + WOFF_W2, 3072, 768);

        layernorm_split_k<<<ROWS, 256>>>(ph, l1g, l1b, pyh, pyl);
        wgemm_k<0><<<dim3(18, mt), 256, WG_SMEM>>>(
            pyh, pyl, pwh + WOFF_QKV, pwl + WOFF_QKV,
            qb, nullptr, pq, nullptr, nullptr, ROWS, 2304, 768);
        attn_scores_k<<<dim3(5, 19, BATCH * NHEAD), 128>>>();
        softmax_k<<<BATCH * NHEAD * NTOK, 128>>>();
        attn_av_k<<<dim3(10, BATCH * NHEAD), 128>>>();
        wgemm_k<1><<<dim3(6, mt), 256, WG_SMEM>>>(
            poh, pol, pwh + WOFF_PROJ, pwl + WOFF_PROJ,
            pb, ph, ph, nullptr, nullptr, ROWS, 768, 768);
        layernorm_split_k<<<ROWS, 256>>>(ph, l2g, l2b, pyh, pyl);
        wgemm_k<2><<<dim3(24, mt), 256, WG_SMEM>>>(
            pyh, pyl, pwh + WOFF_W1, pwl + WOFF_W1,
            mb1, nullptr, nullptr, pmh, pml, ROWS, 3072, 768);
        wgemm_k<1><<<dim3(6, mt), 256, WG_SMEM>>>(
            pmh, pml, pwh + WOFF_W2, pwl + WOFF_W2,
            mb2, ph, ph, nullptr, nullptr, ROWS, 768, 3072);
    }

    layernorm_k<<<BATCH, 256>>>(ph, (size_t)NTOK * DIMN, lnf_g, lnf_b, pc, 1e-6f);
    head_k<<<BATCH, 256>>>(head_w, head_b, out);
}